// round 6
// baseline (speedup 1.0000x reference)
#include <cuda_runtime.h>
#include <math_constants.h>

#define NFEAT 65536
#define FD    512
#define NC    256
#define RPC   (NFEAT / NC)      // 256 rows per class
#define F4D   (FD / 4)          // 128 float4 per row
#define RSPLIT 8                // row-chunks per class
#define RCHUNK (RPC / RSPLIT)   // 32 rows per chunk
#define NBLK2  (NC / 4)         // 64 sim blocks

// Scratch (no cudaMalloc allowed)
__device__ float g_partial[RSPLIT * NC * FD];  // 4 MB partial sums
__device__ float g_centers[NC * FD];           // normalized centers [j][k]
__device__ float g_centersT[FD * NC];          // normalized centers [k][j]
__device__ float g_rowval[NC];                 // per-row (1 - min_off_diag)
__device__ unsigned int g_done;                // centers-ready counter
__device__ unsigned int g_cnt2;                // sim fan-in counter

// ---------------------------------------------------------------------------
// Kernel 1: partial row-sums. grid = NC*RSPLIT = 2048 blocks, 128 threads.
// Block b: class c = b>>3, chunk s = b&7. Streaming __ldcs, fully coalesced.
// ---------------------------------------------------------------------------
__global__ void __launch_bounds__(128) centers_partial_kernel(const float* __restrict__ feat) {
    const int b = blockIdx.x;
    const int c = b >> 3;
    const int s = b & 7;
    const int t = threadIdx.x;                 // 0..127

    const float4* __restrict__ p =
        reinterpret_cast<const float4*>(feat)
        + ((size_t)c * RPC + (size_t)s * RCHUNK) * F4D + t;

    float4 acc = make_float4(0.f, 0.f, 0.f, 0.f);
    #pragma unroll 8
    for (int r = 0; r < RCHUNK; ++r) {
        float4 v = __ldcs(p + (size_t)r * F4D);
        acc.x += v.x; acc.y += v.y; acc.z += v.z; acc.w += v.w;
    }
    reinterpret_cast<float4*>(g_partial)[((size_t)s * NC + c) * F4D + t] = acc;
}

// ---------------------------------------------------------------------------
// Kernel 2: fused finalize + sim + final sum. grid = 64, block = 256.
// Phase A: block b finalizes its own 4 classes (ib..ib+3): fold RSPLIT
//          partials, mean, L2-norm; write g_centers, g_centersT, and the
//          block's own smem i-tile directly.
// Phase B: arrive-and-spin until all 64 blocks finished Phase A (all blocks
//          co-resident on 148 SMs -> safe).
// Phase C: register double-buffered CT mat-vec, off-diag row mins.
// Phase D: fan-in: last block sums (1 - min) into out[0], resets counters.
// ---------------------------------------------------------------------------
#define SIM_STEP(AV0, AV1, AV2, AV3, V)                                      \
    acc[0][0] += (AV0)*(V).x; acc[0][1] += (AV0)*(V).y;                      \
    acc[0][2] += (AV0)*(V).z; acc[0][3] += (AV0)*(V).w;                      \
    acc[1][0] += (AV1)*(V).x; acc[1][1] += (AV1)*(V).y;                      \
    acc[1][2] += (AV1)*(V).z; acc[1][3] += (AV1)*(V).w;                      \
    acc[2][0] += (AV2)*(V).x; acc[2][1] += (AV2)*(V).y;                      \
    acc[2][2] += (AV2)*(V).z; acc[2][3] += (AV2)*(V).w;                      \
    acc[3][0] += (AV3)*(V).x; acc[3][1] += (AV3)*(V).y;                      \
    acc[3][2] += (AV3)*(V).z; acc[3][3] += (AV3)*(V).w;

__global__ void __launch_bounds__(256) sim_kernel(float* __restrict__ out) {
    const int b  = blockIdx.x;
    const int ib = b * 4;                      // i rows / classes [ib, ib+4)
    const int t  = threadIdx.x;
    const int jq = t & 63;
    const int ks = t >> 6;

    __shared__ float4 sc4[4][F4D];             // 8 KB: this block's i-rows
    __shared__ float4 red4[256 * 4];           // 16 KB: per-thread partials
    __shared__ float  sred[8];

    // ---- Phase A: finalize 4 classes (2 per round, 128 threads each) ----
    {
        const int half = t >> 7;               // 0 or 1
        const int tt   = t & 127;              // float4 column
        const int lane = t & 31;
        #pragma unroll
        for (int round = 0; round < 2; ++round) {
            const int c   = ib + round * 2 + half;
            const int row = round * 2 + half;  // local i-row index

            float4 sum = make_float4(0.f, 0.f, 0.f, 0.f);
            #pragma unroll
            for (int k = 0; k < RSPLIT; ++k) {
                float4 v = __ldcg(reinterpret_cast<const float4*>(g_partial)
                                  + ((size_t)k * NC + c) * F4D + tt);
                sum.x += v.x; sum.y += v.y; sum.z += v.z; sum.w += v.w;
            }
            const float inv = 1.0f / (float)RPC;
            sum.x *= inv; sum.y *= inv; sum.z *= inv; sum.w *= inv;

            float ss = sum.x*sum.x + sum.y*sum.y + sum.z*sum.z + sum.w*sum.w;
            #pragma unroll
            for (int o = 16; o > 0; o >>= 1)
                ss += __shfl_xor_sync(0xffffffffu, ss, o);
            if (lane == 0) sred[t >> 5] = ss;
            __syncthreads();
            float total = sred[half*4+0] + sred[half*4+1] + sred[half*4+2] + sred[half*4+3];
            float invn = 1.0f / fmaxf(sqrtf(total), 1e-8f);

            float4 o4 = make_float4(sum.x*invn, sum.y*invn, sum.z*invn, sum.w*invn);
            reinterpret_cast<float4*>(g_centers)[(size_t)c * F4D + tt] = o4;
            g_centersT[(size_t)(4*tt + 0) * NC + c] = o4.x;
            g_centersT[(size_t)(4*tt + 1) * NC + c] = o4.y;
            g_centersT[(size_t)(4*tt + 2) * NC + c] = o4.z;
            g_centersT[(size_t)(4*tt + 3) * NC + c] = o4.w;
            sc4[row][tt] = o4;
            __syncthreads();                   // sred reuse next round
        }
    }

    // ---- Phase B: grid-wide readiness barrier (64 co-resident blocks) ----
    __threadfence();
    if (t == 0) {
        atomicAdd(&g_done, 1u);
        while (atomicAdd(&g_done, 0u) < (unsigned)NBLK2) { __nanosleep(64); }
    }
    __syncthreads();

    // ---- Phase C: sim main loop ----
    const float4* __restrict__ ct = reinterpret_cast<const float4*>(g_centersT);

    float acc[4][4];
    #pragma unroll
    for (int i = 0; i < 4; ++i)
        #pragma unroll
        for (int j = 0; j < 4; ++j) acc[i][j] = 0.f;

    const int kb = ks * 128;
    float4 buf[2][8];
    #pragma unroll
    for (int u = 0; u < 8; ++u)
        buf[0][u] = __ldcg(&ct[(size_t)(kb + u) * (NC / 4) + jq]);

    #pragma unroll 2
    for (int ch = 0; ch < 16; ++ch) {
        const int pb = ch & 1;
        if (ch < 15) {
            const int k2 = kb + (ch + 1) * 8;
            #pragma unroll
            for (int u = 0; u < 8; ++u)
                buf[pb ^ 1][u] = __ldcg(&ct[(size_t)(k2 + u) * (NC / 4) + jq]);
        }
        const int kf0 = (kb + ch * 8) >> 2;
        #pragma unroll
        for (int g = 0; g < 2; ++g) {
            const int kf = kf0 + g;
            float4 a0 = sc4[0][kf];
            float4 a1 = sc4[1][kf];
            float4 a2 = sc4[2][kf];
            float4 a3 = sc4[3][kf];
            SIM_STEP(a0.x, a1.x, a2.x, a3.x, buf[pb][g * 4 + 0]);
            SIM_STEP(a0.y, a1.y, a2.y, a3.y, buf[pb][g * 4 + 1]);
            SIM_STEP(a0.z, a1.z, a2.z, a3.z, buf[pb][g * 4 + 2]);
            SIM_STEP(a0.w, a1.w, a2.w, a3.w, buf[pb][g * 4 + 3]);
        }
    }

    #pragma unroll
    for (int i = 0; i < 4; ++i)
        red4[(size_t)t * 4 + i] = make_float4(acc[i][0], acc[i][1], acc[i][2], acc[i][3]);
    __syncthreads();

    __shared__ float s_minw[2][4];
    if (t < 64) {                              // jq == t
        float mn[4];
        #pragma unroll
        for (int i = 0; i < 4; ++i) {
            float4 a = red4[(size_t)(0 * 64 + t) * 4 + i];
            float4 bb = red4[(size_t)(1 * 64 + t) * 4 + i];
            float4 cc = red4[(size_t)(2 * 64 + t) * 4 + i];
            float4 d = red4[(size_t)(3 * 64 + t) * 4 + i];
            float sx = a.x + bb.x + cc.x + d.x;
            float sy = a.y + bb.y + cc.y + d.y;
            float sz = a.z + bb.z + cc.z + d.z;
            float sw = a.w + bb.w + cc.w + d.w;
            const int ig = ib + i;
            float m = CUDART_INF_F;
            if (4 * t + 0 != ig) m = fminf(m, sx);
            if (4 * t + 1 != ig) m = fminf(m, sy);
            if (4 * t + 2 != ig) m = fminf(m, sz);
            if (4 * t + 3 != ig) m = fminf(m, sw);
            mn[i] = m;
        }
        #pragma unroll
        for (int o = 16; o > 0; o >>= 1) {
            #pragma unroll
            for (int i = 0; i < 4; ++i)
                mn[i] = fminf(mn[i], __shfl_xor_sync(0xffffffffu, mn[i], o));
        }
        if ((t & 31) == 0) {
            #pragma unroll
            for (int i = 0; i < 4; ++i) s_minw[t >> 5][i] = mn[i];
        }
    }
    __syncthreads();
    if (t < 4)
        g_rowval[ib + t] = 1.0f - fminf(s_minw[0][t], s_minw[1][t]);

    // ---- Phase D: fan-in final sum ----
    __threadfence();
    __shared__ unsigned int s_prev;
    if (t == 0) s_prev = atomicAdd(&g_cnt2, 1u);
    __syncthreads();
    if (s_prev != NBLK2 - 1) return;
    __threadfence();

    float v = __ldcg(&g_rowval[t]);
    #pragma unroll
    for (int o = 16; o > 0; o >>= 1)
        v += __shfl_xor_sync(0xffffffffu, v, o);

    __shared__ float sfin[8];
    if ((t & 31) == 0) sfin[t >> 5] = v;
    __syncthreads();
    if (t == 0) {
        float total = 0.f;
        #pragma unroll
        for (int i = 0; i < 8; ++i) total += sfin[i];
        out[0] = total;
        g_cnt2 = 0u;   // reset for next graph replay
        g_done = 0u;
    }
}

extern "C" void kernel_launch(void* const* d_in, const int* in_sizes, int n_in,
                              void* d_out, int out_size) {
    const float* feat = (const float*)d_in[0];
    float* out = (float*)d_out;

    centers_partial_kernel<<<NC * RSPLIT, 128>>>(feat);
    sim_kernel<<<NBLK2, 256>>>(out);
}

// round 7
// speedup vs baseline: 1.1223x; 1.1223x over previous
#include <cuda_runtime.h>
#include <math_constants.h>

#define NFEAT 65536
#define FD    512
#define NC    256
#define RPC   (NFEAT / NC)      // 256 rows per class
#define F4D   (FD / 4)          // 128 float4 per row
#define RSPLIT 8                // row-chunks per class
#define RCHUNK (RPC / RSPLIT)   // 32 rows per chunk
#define NJT    4                // j-tiles in sim
#define NBLK2  (64 * NJT)       // 256 sim blocks

// Scratch (no cudaMalloc allowed)
__device__ float g_partial[RSPLIT * NC * FD];  // 4 MB partial sums
__device__ float g_centers[NC * FD];           // normalized centers [j][k]
__device__ float g_centersT[FD * NC];          // normalized centers [k][j]
__device__ float g_partmin[NJT * NC];          // per-(jtile,row) partial min
__device__ unsigned int g_cnt2;                // sim fan-in counter

// ---------------------------------------------------------------------------
// Kernel 1: partial row-sums. grid = NC*RSPLIT = 2048 blocks, 128 threads.
// ---------------------------------------------------------------------------
__global__ void __launch_bounds__(128) centers_partial_kernel(const float* __restrict__ feat) {
    const int b = blockIdx.x;
    const int c = b >> 3;
    const int s = b & 7;
    const int t = threadIdx.x;

    const float4* __restrict__ p =
        reinterpret_cast<const float4*>(feat)
        + ((size_t)c * RPC + (size_t)s * RCHUNK) * F4D + t;

    float4 acc = make_float4(0.f, 0.f, 0.f, 0.f);
    #pragma unroll 8
    for (int r = 0; r < RCHUNK; ++r) {
        float4 v = __ldcs(p + (size_t)r * F4D);
        acc.x += v.x; acc.y += v.y; acc.z += v.z; acc.w += v.w;
    }
    reinterpret_cast<float4*>(g_partial)[((size_t)s * NC + c) * F4D + t] = acc;
}

// ---------------------------------------------------------------------------
// Kernel 2: fold partials, mean, L2-norm; write row-major + transposed.
// grid = 256, block = 128.
// ---------------------------------------------------------------------------
__global__ void __launch_bounds__(128) centers_finalize_kernel() {
    const int c = blockIdx.x;
    const int t = threadIdx.x;

    float4 sum = make_float4(0.f, 0.f, 0.f, 0.f);
    #pragma unroll
    for (int k = 0; k < RSPLIT; ++k) {
        float4 v = reinterpret_cast<const float4*>(g_partial)[((size_t)k * NC + c) * F4D + t];
        sum.x += v.x; sum.y += v.y; sum.z += v.z; sum.w += v.w;
    }
    const float inv = 1.0f / (float)RPC;
    sum.x *= inv; sum.y *= inv; sum.z *= inv; sum.w *= inv;

    float ss = sum.x*sum.x + sum.y*sum.y + sum.z*sum.z + sum.w*sum.w;
    #pragma unroll
    for (int o = 16; o > 0; o >>= 1)
        ss += __shfl_xor_sync(0xffffffffu, ss, o);

    __shared__ float sred[4];
    if ((t & 31) == 0) sred[t >> 5] = ss;
    __syncthreads();
    float total = sred[0] + sred[1] + sred[2] + sred[3];
    float invn = 1.0f / fmaxf(sqrtf(total), 1e-8f);

    float4 o4 = make_float4(sum.x * invn, sum.y * invn, sum.z * invn, sum.w * invn);
    reinterpret_cast<float4*>(g_centers)[(size_t)c * F4D + t] = o4;

    g_centersT[(size_t)(4 * t + 0) * NC + c] = o4.x;
    g_centersT[(size_t)(4 * t + 1) * NC + c] = o4.y;
    g_centersT[(size_t)(4 * t + 2) * NC + c] = o4.z;
    g_centersT[(size_t)(4 * t + 3) * NC + c] = o4.w;
}

// ---------------------------------------------------------------------------
// Kernel 3: sim partial row mins, j-tiled across 256 blocks + fan-in sum.
// Block blk: i-tile bi = blk & 63 (rows ib..ib+3), j-tile jt = blk >> 6
// (j in [64jt, 64jt+64)). 256 threads: jq = t&15 owns float4 j-group
// (j = 64jt+4jq..+3), ks = t>>4 owns k-slice [32ks, 32ks+32).
// Double-buffered CT loads; 16 accumulators; per-block min -> g_partmin.
// Last block: min over 4 j-tiles per row, sum(1 - min) -> out[0].
// ---------------------------------------------------------------------------
#define SIM_STEP(AV0, AV1, AV2, AV3, V)                                      \
    acc[0][0] += (AV0)*(V).x; acc[0][1] += (AV0)*(V).y;                      \
    acc[0][2] += (AV0)*(V).z; acc[0][3] += (AV0)*(V).w;                      \
    acc[1][0] += (AV1)*(V).x; acc[1][1] += (AV1)*(V).y;                      \
    acc[1][2] += (AV1)*(V).z; acc[1][3] += (AV1)*(V).w;                      \
    acc[2][0] += (AV2)*(V).x; acc[2][1] += (AV2)*(V).y;                      \
    acc[2][2] += (AV2)*(V).z; acc[2][3] += (AV2)*(V).w;                      \
    acc[3][0] += (AV3)*(V).x; acc[3][1] += (AV3)*(V).y;                      \
    acc[3][2] += (AV3)*(V).z; acc[3][3] += (AV3)*(V).w;

__global__ void __launch_bounds__(256) sim_kernel(float* __restrict__ out) {
    const int blk = blockIdx.x;
    const int bi  = blk & 63;
    const int jt  = blk >> 6;
    const int ib  = bi * 4;                    // i rows [ib, ib+4)
    const int t   = threadIdx.x;
    const int jq  = t & 15;                    // j float4-group within tile
    const int ks  = t >> 4;                    // k-slice 0..15

    __shared__ float4 sc4[4][F4D];             // 8 KB: i-rows
    __shared__ float4 red4[256 * 4];           // 16 KB: per-thread partials
    {
        const float4* src = reinterpret_cast<const float4*>(g_centers + (size_t)ib * FD);
        #pragma unroll
        for (int k = t; k < 4 * F4D; k += 256)
            sc4[k >> 7][k & 127] = src[k];
    }
    __syncthreads();

    const float4* __restrict__ ct = reinterpret_cast<const float4*>(g_centersT);
    const int col = jt * 16 + jq;              // float4 column in CT row

    float acc[4][4];
    #pragma unroll
    for (int i = 0; i < 4; ++i)
        #pragma unroll
        for (int j = 0; j < 4; ++j) acc[i][j] = 0.f;

    const int kb = ks * 32;
    float4 buf[2][8];
    #pragma unroll
    for (int u = 0; u < 8; ++u)
        buf[0][u] = __ldcg(&ct[(size_t)(kb + u) * (NC / 4) + col]);

    #pragma unroll
    for (int ch = 0; ch < 4; ++ch) {
        const int pb = ch & 1;
        if (ch < 3) {
            const int k2 = kb + (ch + 1) * 8;
            #pragma unroll
            for (int u = 0; u < 8; ++u)
                buf[pb ^ 1][u] = __ldcg(&ct[(size_t)(k2 + u) * (NC / 4) + col]);
        }
        const int kf0 = (kb + ch * 8) >> 2;
        #pragma unroll
        for (int g = 0; g < 2; ++g) {
            const int kf = kf0 + g;
            float4 a0 = sc4[0][kf];
            float4 a1 = sc4[1][kf];
            float4 a2 = sc4[2][kf];
            float4 a3 = sc4[3][kf];
            SIM_STEP(a0.x, a1.x, a2.x, a3.x, buf[pb][g * 4 + 0]);
            SIM_STEP(a0.y, a1.y, a2.y, a3.y, buf[pb][g * 4 + 1]);
            SIM_STEP(a0.z, a1.z, a2.z, a3.z, buf[pb][g * 4 + 2]);
            SIM_STEP(a0.w, a1.w, a2.w, a3.w, buf[pb][g * 4 + 3]);
        }
    }

    #pragma unroll
    for (int i = 0; i < 4; ++i)
        red4[(size_t)t * 4 + i] = make_float4(acc[i][0], acc[i][1], acc[i][2], acc[i][3]);
    __syncthreads();

    __shared__ float s_min[4][16];
    if (t < 64) {                              // thread = (i = t>>4, jq2 = t&15)
        const int i   = t >> 4;
        const int jq2 = t & 15;
        float4 s = make_float4(0.f, 0.f, 0.f, 0.f);
        #pragma unroll
        for (int k2 = 0; k2 < 16; ++k2) {
            float4 v = red4[(size_t)(k2 * 16 + jq2) * 4 + i];
            s.x += v.x; s.y += v.y; s.z += v.z; s.w += v.w;
        }
        const int ig = ib + i;
        const int jb = jt * 64 + 4 * jq2;
        float m = CUDART_INF_F;
        if (jb + 0 != ig) m = fminf(m, s.x);
        if (jb + 1 != ig) m = fminf(m, s.y);
        if (jb + 2 != ig) m = fminf(m, s.z);
        if (jb + 3 != ig) m = fminf(m, s.w);
        s_min[i][jq2] = m;
    }
    __syncthreads();
    if (t < 4) {
        float m = CUDART_INF_F;
        #pragma unroll
        for (int q = 0; q < 16; ++q) m = fminf(m, s_min[t][q]);
        g_partmin[(size_t)jt * NC + ib + t] = m;
    }

    // fan-in: last block computes sum(1 - min over jt) into out[0]
    __threadfence();
    __shared__ unsigned int s_prev;
    if (t == 0) s_prev = atomicAdd(&g_cnt2, 1u);
    __syncthreads();
    if (s_prev != NBLK2 - 1) return;
    __threadfence();

    float m = __ldcg(&g_partmin[t]);
    #pragma unroll
    for (int jt2 = 1; jt2 < NJT; ++jt2)
        m = fminf(m, __ldcg(&g_partmin[(size_t)jt2 * NC + t]));
    float v = 1.0f - m;

    #pragma unroll
    for (int o = 16; o > 0; o >>= 1)
        v += __shfl_xor_sync(0xffffffffu, v, o);

    __shared__ float sfin[8];
    if ((t & 31) == 0) sfin[t >> 5] = v;
    __syncthreads();
    if (t == 0) {
        float total = 0.f;
        #pragma unroll
        for (int i = 0; i < 8; ++i) total += sfin[i];
        out[0] = total;
        g_cnt2 = 0u;   // reset for next graph replay
    }
}

extern "C" void kernel_launch(void* const* d_in, const int* in_sizes, int n_in,
                              void* d_out, int out_size) {
    const float* feat = (const float*)d_in[0];
    float* out = (float*)d_out;

    centers_partial_kernel<<<NC * RSPLIT, 128>>>(feat);
    centers_finalize_kernel<<<NC, 128>>>();
    sim_kernel<<<NBLK2, 256>>>(out);
}

// round 8
// speedup vs baseline: 1.1233x; 1.0009x over previous
#include <cuda_runtime.h>
#include <math_constants.h>

#define NFEAT 65536
#define FD    512
#define NC    256
#define RPC   (NFEAT / NC)      // 256 rows per class
#define F4D   (FD / 4)          // 128 float4 per row
#define RSPLIT 8                // row-chunks per class
#define RCHUNK (RPC / RSPLIT)   // 32 rows per chunk
#define NJT    4                // j-tiles in sim
#define NBLK2  (64 * NJT)       // 256 sim blocks

// Scratch (no cudaMalloc allowed)
__device__ float g_partial[RSPLIT * NC * FD];  // 4 MB partial sums
__device__ float g_centers[NC * FD];           // normalized centers [j][k]
__device__ float g_centersT[FD * NC];          // normalized centers [k][j]
__device__ float g_partmin[NJT * NC];          // per-(jtile,row) partial min
__device__ unsigned int g_done;                // centers-ready barrier counter
__device__ unsigned int g_cnt2;                // sim fan-in counter

// ---------------------------------------------------------------------------
// Kernel 1: partial row-sums. grid = 2048, block = 128.
// Explicit 8-deep load batching: 8 independent LDG.128 issued before any
// consumption -> MLP_eff ~8/thread (regs ~48, occ ~62%, in-flight 2x R7).
// ---------------------------------------------------------------------------
__global__ void __launch_bounds__(128) centers_partial_kernel(const float* __restrict__ feat) {
    const int b = blockIdx.x;
    const int c = b >> 3;
    const int s = b & 7;
    const int t = threadIdx.x;

    const float4* __restrict__ p =
        reinterpret_cast<const float4*>(feat)
        + ((size_t)c * RPC + (size_t)s * RCHUNK) * F4D + t;

    float4 acc = make_float4(0.f, 0.f, 0.f, 0.f);
    #pragma unroll
    for (int r0 = 0; r0 < RCHUNK; r0 += 8) {
        float4 b0 = __ldcs(p + (size_t)(r0 + 0) * F4D);
        float4 b1 = __ldcs(p + (size_t)(r0 + 1) * F4D);
        float4 b2 = __ldcs(p + (size_t)(r0 + 2) * F4D);
        float4 b3 = __ldcs(p + (size_t)(r0 + 3) * F4D);
        float4 b4 = __ldcs(p + (size_t)(r0 + 4) * F4D);
        float4 b5 = __ldcs(p + (size_t)(r0 + 5) * F4D);
        float4 b6 = __ldcs(p + (size_t)(r0 + 6) * F4D);
        float4 b7 = __ldcs(p + (size_t)(r0 + 7) * F4D);
        acc.x += b0.x; acc.y += b0.y; acc.z += b0.z; acc.w += b0.w;
        acc.x += b1.x; acc.y += b1.y; acc.z += b1.z; acc.w += b1.w;
        acc.x += b2.x; acc.y += b2.y; acc.z += b2.z; acc.w += b2.w;
        acc.x += b3.x; acc.y += b3.y; acc.z += b3.z; acc.w += b3.w;
        acc.x += b4.x; acc.y += b4.y; acc.z += b4.z; acc.w += b4.w;
        acc.x += b5.x; acc.y += b5.y; acc.z += b5.z; acc.w += b5.w;
        acc.x += b6.x; acc.y += b6.y; acc.z += b6.z; acc.w += b6.w;
        acc.x += b7.x; acc.y += b7.y; acc.z += b7.z; acc.w += b7.w;
    }
    reinterpret_cast<float4*>(g_partial)[((size_t)s * NC + c) * F4D + t] = acc;
}

// ---------------------------------------------------------------------------
// Kernel 2: fused finalize + sim + final sum. grid = 256, block = 256.
// Phase A: block blk finalizes class blk (fold 8 partials, mean, L2-norm,
//          write g_centers row + g_centersT columns). 128 active threads.
// Phase B: grid-wide arrive-and-spin barrier (256 blocks, all co-resident:
//          2 blocks/SM x 148 SMs = 296 slots).
// Phase C: j-tiled sim (bi = blk&63 -> i-rows 4bi..4bi+3; jt = blk>>6 ->
//          j in [64jt, 64jt+64)); double-buffered __ldcg CT loads.
// Phase D: fan-in: last block min-reduces over j-tiles, sums into out[0].
// ---------------------------------------------------------------------------
#define SIM_STEP(AV0, AV1, AV2, AV3, V)                                      \
    acc[0][0] += (AV0)*(V).x; acc[0][1] += (AV0)*(V).y;                      \
    acc[0][2] += (AV0)*(V).z; acc[0][3] += (AV0)*(V).w;                      \
    acc[1][0] += (AV1)*(V).x; acc[1][1] += (AV1)*(V).y;                      \
    acc[1][2] += (AV1)*(V).z; acc[1][3] += (AV1)*(V).w;                      \
    acc[2][0] += (AV2)*(V).x; acc[2][1] += (AV2)*(V).y;                      \
    acc[2][2] += (AV2)*(V).z; acc[2][3] += (AV2)*(V).w;                      \
    acc[3][0] += (AV3)*(V).x; acc[3][1] += (AV3)*(V).y;                      \
    acc[3][2] += (AV3)*(V).z; acc[3][3] += (AV3)*(V).w;

__global__ void __launch_bounds__(256) sim_kernel(float* __restrict__ out) {
    const int blk = blockIdx.x;
    const int bi  = blk & 63;
    const int jt  = blk >> 6;
    const int ib  = bi * 4;                    // i rows [ib, ib+4)
    const int t   = threadIdx.x;

    // ---- Phase A: finalize class c = blk (threads 0..127 active) ----
    __shared__ float sredA[4];
    if (t < 128) {
        const int c = blk;
        float4 sum = make_float4(0.f, 0.f, 0.f, 0.f);
        #pragma unroll
        for (int k = 0; k < RSPLIT; ++k) {
            float4 v = __ldcg(reinterpret_cast<const float4*>(g_partial)
                              + ((size_t)k * NC + c) * F4D + t);
            sum.x += v.x; sum.y += v.y; sum.z += v.z; sum.w += v.w;
        }
        const float inv = 1.0f / (float)RPC;
        sum.x *= inv; sum.y *= inv; sum.z *= inv; sum.w *= inv;

        float ss = sum.x*sum.x + sum.y*sum.y + sum.z*sum.z + sum.w*sum.w;
        #pragma unroll
        for (int o = 16; o > 0; o >>= 1)
            ss += __shfl_xor_sync(0xffffffffu, ss, o);
        if ((t & 31) == 0) sredA[t >> 5] = ss;
        __syncwarp();
        // need all 4 warps' partials: sync the 128 threads via bar below
        __syncthreads();
        float total = sredA[0] + sredA[1] + sredA[2] + sredA[3];
        float invn = 1.0f / fmaxf(sqrtf(total), 1e-8f);

        float4 o4 = make_float4(sum.x*invn, sum.y*invn, sum.z*invn, sum.w*invn);
        reinterpret_cast<float4*>(g_centers)[(size_t)c * F4D + t] = o4;
        g_centersT[(size_t)(4*t + 0) * NC + c] = o4.x;
        g_centersT[(size_t)(4*t + 1) * NC + c] = o4.y;
        g_centersT[(size_t)(4*t + 2) * NC + c] = o4.z;
        g_centersT[(size_t)(4*t + 3) * NC + c] = o4.w;
    } else {
        __syncthreads();                       // match Phase A barrier
    }

    // ---- Phase B: grid-wide readiness barrier ----
    __threadfence();
    if (t == 0) {
        atomicAdd(&g_done, 1u);
        while (atomicAdd(&g_done, 0u) < (unsigned)NBLK2) { __nanosleep(32); }
    }
    __syncthreads();

    // ---- Phase C: j-tiled sim ----
    const int jq = t & 15;                     // j float4-group within tile
    const int ks = t >> 4;                     // k-slice 0..15

    __shared__ float4 sc4[4][F4D];             // 8 KB: i-rows
    __shared__ float4 red4[256 * 4];           // 16 KB: per-thread partials
    {
        const float4* src = reinterpret_cast<const float4*>(g_centers + (size_t)ib * FD);
        #pragma unroll
        for (int k = t; k < 4 * F4D; k += 256)
            sc4[k >> 7][k & 127] = __ldcg(src + k);
    }
    __syncthreads();

    const float4* __restrict__ ct = reinterpret_cast<const float4*>(g_centersT);
    const int col = jt * 16 + jq;

    float acc[4][4];
    #pragma unroll
    for (int i = 0; i < 4; ++i)
        #pragma unroll
        for (int j = 0; j < 4; ++j) acc[i][j] = 0.f;

    const int kb = ks * 32;
    float4 buf[2][8];
    #pragma unroll
    for (int u = 0; u < 8; ++u)
        buf[0][u] = __ldcg(&ct[(size_t)(kb + u) * (NC / 4) + col]);

    #pragma unroll
    for (int ch = 0; ch < 4; ++ch) {
        const int pb = ch & 1;
        if (ch < 3) {
            const int k2 = kb + (ch + 1) * 8;
            #pragma unroll
            for (int u = 0; u < 8; ++u)
                buf[pb ^ 1][u] = __ldcg(&ct[(size_t)(k2 + u) * (NC / 4) + col]);
        }
        const int kf0 = (kb + ch * 8) >> 2;
        #pragma unroll
        for (int g = 0; g < 2; ++g) {
            const int kf = kf0 + g;
            float4 a0 = sc4[0][kf];
            float4 a1 = sc4[1][kf];
            float4 a2 = sc4[2][kf];
            float4 a3 = sc4[3][kf];
            SIM_STEP(a0.x, a1.x, a2.x, a3.x, buf[pb][g * 4 + 0]);
            SIM_STEP(a0.y, a1.y, a2.y, a3.y, buf[pb][g * 4 + 1]);
            SIM_STEP(a0.z, a1.z, a2.z, a3.z, buf[pb][g * 4 + 2]);
            SIM_STEP(a0.w, a1.w, a2.w, a3.w, buf[pb][g * 4 + 3]);
        }
    }

    #pragma unroll
    for (int i = 0; i < 4; ++i)
        red4[(size_t)t * 4 + i] = make_float4(acc[i][0], acc[i][1], acc[i][2], acc[i][3]);
    __syncthreads();

    __shared__ float s_min[4][16];
    if (t < 64) {                              // thread = (i = t>>4, jq2 = t&15)
        const int i   = t >> 4;
        const int jq2 = t & 15;
        float4 s = make_float4(0.f, 0.f, 0.f, 0.f);
        #pragma unroll
        for (int k2 = 0; k2 < 16; ++k2) {
            float4 v = red4[(size_t)(k2 * 16 + jq2) * 4 + i];
            s.x += v.x; s.y += v.y; s.z += v.z; s.w += v.w;
        }
        const int ig = ib + i;
        const int jb = jt * 64 + 4 * jq2;
        float m = CUDART_INF_F;
        if (jb + 0 != ig) m = fminf(m, s.x);
        if (jb + 1 != ig) m = fminf(m, s.y);
        if (jb + 2 != ig) m = fminf(m, s.z);
        if (jb + 3 != ig) m = fminf(m, s.w);
        s_min[i][jq2] = m;
    }
    __syncthreads();
    if (t < 4) {
        float m = CUDART_INF_F;
        #pragma unroll
        for (int q = 0; q < 16; ++q) m = fminf(m, s_min[t][q]);
        g_partmin[(size_t)jt * NC + ib + t] = m;
    }

    // ---- Phase D: fan-in final sum ----
    __threadfence();
    __shared__ unsigned int s_prev;
    if (t == 0) s_prev = atomicAdd(&g_cnt2, 1u);
    __syncthreads();
    if (s_prev != NBLK2 - 1) return;
    __threadfence();

    float m = __ldcg(&g_partmin[t]);
    #pragma unroll
    for (int jt2 = 1; jt2 < NJT; ++jt2)
        m = fminf(m, __ldcg(&g_partmin[(size_t)jt2 * NC + t]));
    float v = 1.0f - m;

    #pragma unroll
    for (int o = 16; o > 0; o >>= 1)
        v += __shfl_xor_sync(0xffffffffu, v, o);

    __shared__ float sfin[8];
    if ((t & 31) == 0) sfin[t >> 5] = v;
    __syncthreads();
    if (t == 0) {
        float total = 0.f;
        #pragma unroll
        for (int i = 0; i < 8; ++i) total += sfin[i];
        out[0] = total;
        g_cnt2 = 0u;   // reset for next graph replay
        g_done = 0u;
    }
}

extern "C" void kernel_launch(void* const* d_in, const int* in_sizes, int n_in,
                              void* d_out, int out_size) {
    const float* feat = (const float*)d_in[0];
    float* out = (float*)d_out;

    centers_partial_kernel<<<NC * RSPLIT, 128>>>(feat);
    sim_kernel<<<NBLK2, 256>>>(out);
}